// round 12
// baseline (speedup 1.0000x reference)
#include <cuda_runtime.h>
#include <cuda_bf16.h>
#include <math.h>
#include <stdint.h>

#define D      128
#define NMAX   200000
#define EMAX   600000
#define GMAX   10000
#define EROWS  128
#define SA     136          // smem tile stride in bf16 elements

// ---------------- scratch (device globals; no runtime allocation) -----------
__device__ float S_Ah [(size_t)NMAX * D];   // A(h)
__device__ float S_Dh [(size_t)NMAX * D];   // D(h) -> h_pre in place
__device__ float S_Eh [(size_t)NMAX * D];   // E(h)
__device__ float S_num[(size_t)NMAX * D];
__device__ float S_den[(size_t)NMAX * D];
__device__ float S_E1 [(size_t)EMAX * D];   // B(e) -> e_pre
__device__ float S_Cu [(size_t)GMAX * D];
__device__ float S_Fu [(size_t)GMAX * D];
__device__ float S_Iu [(size_t)GMAX * D];
__device__ float S_accG [(size_t)GMAX * D];
__device__ float S_accHe[(size_t)GMAX * D];
__device__ float S_cnt[GMAX];
__device__ float S_stats[8 * D];
__device__ int   S_dstg[EMAX];              // a2g[dst[e]]
// transposed bf16 split weights: [9][n=128][k=128]
__device__ __align__(16) __nv_bfloat16 S_Wh[9 * D * D];
__device__ __align__(16) __nv_bfloat16 S_Wl[9 * D * D];

// ---------------- helpers ----------------------------------------------------
__device__ __forceinline__ uint32_t smem_u32(const void* p) {
    uint32_t a;
    asm("{ .reg .u64 t; cvta.to.shared.u64 t, %1; cvt.u32.u64 %0, t; }"
        : "=r"(a) : "l"(p));
    return a;
}
__device__ __forceinline__ void ldm_x4(uint32_t& r0, uint32_t& r1,
                                       uint32_t& r2, uint32_t& r3, uint32_t a) {
    asm volatile("ldmatrix.sync.aligned.m8n8.x4.shared.b16 {%0,%1,%2,%3}, [%4];"
                 : "=r"(r0), "=r"(r1), "=r"(r2), "=r"(r3) : "r"(a));
}
__device__ __forceinline__ void mma16816(float* c, const uint32_t* a,
                                         const uint32_t* b) {
    asm volatile(
        "mma.sync.aligned.m16n8k16.row.col.f32.bf16.bf16.f32 "
        "{%0,%1,%2,%3}, {%4,%5,%6,%7}, {%8,%9}, {%0,%1,%2,%3};"
        : "+f"(c[0]), "+f"(c[1]), "+f"(c[2]), "+f"(c[3])
        : "r"(a[0]), "r"(a[1]), "r"(a[2]), "r"(a[3]), "r"(b[0]), "r"(b[1]));
}
__device__ __forceinline__ void red_add_v4(float* p, float4 v) {
    asm volatile("red.global.add.v4.f32 [%0], {%1,%2,%3,%4};"
                 :: "l"(p), "f"(v.x), "f"(v.y), "f"(v.z), "f"(v.w) : "memory");
}
__device__ __forceinline__ void cpa16(uint32_t dst, const void* src) {
    asm volatile("cp.async.cg.shared.global [%0], [%1], 16;"
                 :: "r"(dst), "l"(src) : "memory");
}
__device__ __forceinline__ void cpa16z(uint32_t dst, const void* src, int sbytes) {
    asm volatile("cp.async.cg.shared.global [%0], [%1], 16, %2;"
                 :: "r"(dst), "l"(src), "r"(sbytes) : "memory");
}
__device__ __forceinline__ void cpa_commit() {
    asm volatile("cp.async.commit_group;" ::: "memory");
}
__device__ __forceinline__ void cpa_wait0() {
    asm volatile("cp.async.wait_group 0;" ::: "memory");
}

// smem layout (bytes): AH | AL | BH | BL | staging(fp32, swizzled) | sg[2][128]
#define TILE_B   (128 * SA * 2)          // 34816
#define OFF_AH   0
#define OFF_AL   (TILE_B)
#define OFF_BH   (2 * TILE_B)
// BL at OFF_BH + TILE_B
#define OFF_ST   (4 * TILE_B)            // 139264, staging 128*512 = 65536
#define OFF_SG   (OFF_ST + 65536)        // 204800
#define SMEM_P   (OFF_SG)                // dense kernel
#define SMEM_PA  (OFF_SG + 1024)         // acc kernel (+2x512B index bufs)

// -------- prep: Wt_hi/Wt_lo[i][n][k] = split(W[i][k][n]) ---------------------
__global__ void prep_w_kernel(const float* __restrict__ W) {
    int t = blockIdx.x * 256 + threadIdx.x;
    if (t >= 9 * D * D) return;
    int i = t >> 14, rem = t & 16383, n = rem >> 7, k = rem & 127;
    float v = W[(i << 14) + (k << 7) + n];
    __nv_bfloat16 h = __float2bfloat16(v);
    S_Wh[t] = h;
    S_Wl[t] = __float2bfloat16(v - __bfloat162float(h));
}

__global__ void dstg_kernel(const int* __restrict__ dst,
                            const int* __restrict__ a2g, int E) {
    int i = blockIdx.x * 256 + threadIdx.x;
    if (i < E) S_dstg[i] = a2g[dst[i]];
}

// ---- building blocks --------------------------------------------------------
__device__ __forceinline__ void prefetch_B(uint32_t sb, int idx, int tid) {
    const int n = tid >> 2, cp4 = tid & 3;
    const __nv_bfloat16* sH = S_Wh + (size_t)idx * 16384 + n * 128 + cp4 * 32;
    const __nv_bfloat16* sL = S_Wl + (size_t)idx * 16384 + n * 128 + cp4 * 32;
    uint32_t dH = sb + OFF_BH + (uint32_t)(n * SA + cp4 * 32) * 2;
    uint32_t dL = dH + TILE_B;
#pragma unroll
    for (int j = 0; j < 4; j++) {
        cpa16(dH + j * 16, sH + j * 8);
        cpa16(dL + j * 16, sL + j * 8);
    }
}

// raw fp32 A -> swizzled staging (zero-fill OOB rows)
__device__ __forceinline__ void prefetch_A_raw(const float* __restrict__ X,
                                               uint32_t sb, int m0, int M,
                                               int tid) {
    const int row = tid >> 2, cp = tid & 3;
    const int gr = m0 + row;
    const int ok = (gr < M) ? 16 : 0;
    const float* xr = X + (size_t)(ok ? gr : 0) * D + cp * 32;
    const uint32_t base = sb + OFF_ST + row * 512;
    const uint32_t sw = ((uint32_t)(row & 7)) << 4;
#pragma unroll
    for (int j = 0; j < 8; j++) {
        uint32_t off = (uint32_t)(cp * 128 + j * 16);
        cpa16z(base + (off ^ sw), xr + j * 4, ok);
    }
}

// staging fp32 -> bf16 hi/lo A tiles
__device__ __forceinline__ void convert_A(char* smem, int tid) {
    const int row = tid >> 2, cp = tid & 3;
    const char* st = smem + OFF_ST + row * 512;
    const uint32_t sw = ((uint32_t)(row & 7)) << 4;
    __nv_bfloat16* aH = (__nv_bfloat16*)(smem + OFF_AH) + row * SA + cp * 32;
    __nv_bfloat16* aL = (__nv_bfloat16*)(smem + OFF_AL) + row * SA + cp * 32;
#pragma unroll
    for (int j = 0; j < 8; j++) {
        uint32_t off = (uint32_t)(cp * 128 + j * 16);
        float4 v = *(const float4*)(st + (off ^ sw));
        __nv_bfloat16 h0 = __float2bfloat16(v.x), h1 = __float2bfloat16(v.y);
        __nv_bfloat16 h2 = __float2bfloat16(v.z), h3 = __float2bfloat16(v.w);
        aH[j * 4 + 0] = h0; aH[j * 4 + 1] = h1;
        aH[j * 4 + 2] = h2; aH[j * 4 + 3] = h3;
        aL[j * 4 + 0] = __float2bfloat16(v.x - __bfloat162float(h0));
        aL[j * 4 + 1] = __float2bfloat16(v.y - __bfloat162float(h1));
        aL[j * 4 + 2] = __float2bfloat16(v.z - __bfloat162float(h2));
        aL[j * 4 + 3] = __float2bfloat16(v.w - __bfloat162float(h3));
    }
}

// per-row graph index prefetch (128 ints = 512B via 32x16B)
__device__ __forceinline__ void prefetch_G(const int* __restrict__ grow,
                                           uint32_t sb, int m0, int M,
                                           int tid, int buf) {
    if (tid < 32) {
        int r0 = m0 + tid * 4;
        int rem = M - r0;
        int bytes = (rem >= 4) ? 16 : ((rem > 0) ? rem * 4 : 0);
        const int* src = grow + (bytes > 0 ? r0 : 0);
        cpa16z(sb + OFF_SG + buf * 512 + tid * 16, src, bytes);
    }
}

__device__ __forceinline__ void kloop(uint32_t sb, const uint32_t* aBase,
                                      const uint32_t* bBase, float c[2][4][4]) {
#pragma unroll
    for (int t = 0; t < 2; t++)
#pragma unroll
        for (int j = 0; j < 4; j++)
#pragma unroll
            for (int q = 0; q < 4; q++) c[t][j][q] = 0.f;
#pragma unroll
    for (int ks = 0; ks < 8; ks++) {
        const uint32_t ko = (uint32_t)(ks * 16) * 2;
        uint32_t ah[2][4], al[2][4];
#pragma unroll
        for (int t = 0; t < 2; t++) {
            ldm_x4(ah[t][0], ah[t][1], ah[t][2], ah[t][3],
                   sb + OFF_AH + aBase[t] + ko);
            ldm_x4(al[t][0], al[t][1], al[t][2], al[t][3],
                   sb + OFF_AL + aBase[t] + ko);
        }
        uint32_t bh[4][2], bl[4][2];
#pragma unroll
        for (int jj = 0; jj < 2; jj++) {
            uint32_t r0, r1, r2, r3;
            ldm_x4(r0, r1, r2, r3, sb + OFF_BH + bBase[jj] + ko);
            bh[jj * 2 + 0][0] = r0; bh[jj * 2 + 0][1] = r1;
            bh[jj * 2 + 1][0] = r2; bh[jj * 2 + 1][1] = r3;
            ldm_x4(r0, r1, r2, r3, sb + OFF_BH + TILE_B + bBase[jj] + ko);
            bl[jj * 2 + 0][0] = r0; bl[jj * 2 + 0][1] = r1;
            bl[jj * 2 + 1][0] = r2; bl[jj * 2 + 1][1] = r3;
        }
#pragma unroll
        for (int t = 0; t < 2; t++)
#pragma unroll
            for (int j = 0; j < 4; j++) {
                mma16816(c[t][j], ah[t], bh[j]);
                mma16816(c[t][j], ah[t], bl[j]);
                mma16816(c[t][j], al[t], bh[j]);
            }
    }
}

// -------- persistent HMMA GEMM, dense output ---------------------------------
__global__ void __launch_bounds__(512, 1) gemm_pers_kernel(
    const float* __restrict__ X, const float* __restrict__ bias9, int idx,
    float* __restrict__ Y, int M)
{
    extern __shared__ char smem[];
    const uint32_t sb = smem_u32(smem);
    const int tid = threadIdx.x, lane = tid & 31, warp = tid >> 5;
    const int wm = warp >> 2, wn = warp & 3;
    const int nT = (M + 127) >> 7;
    if ((int)blockIdx.x >= nT) return;

    prefetch_B(sb, idx, tid);
    prefetch_A_raw(X, sb, blockIdx.x * 128, M, tid);
    cpa_commit();

    const int lt = lane >> 3, lr = lane & 7;
    uint32_t aBase[2];
#pragma unroll
    for (int t = 0; t < 2; t++)
        aBase[t] = (uint32_t)((wm * 32 + t * 16 + (lt & 1) * 8 + lr) * SA
                              + (lt >> 1) * 8) * 2;
    uint32_t bBase[2];
#pragma unroll
    for (int jj = 0; jj < 2; jj++)
        bBase[jj] = (uint32_t)((wn * 32 + jj * 16 + (lt >> 1) * 8 + lr) * SA
                               + (lt & 1) * 8) * 2;

    const float* bv = bias9 + idx * D;
    const int g = lane >> 2, tg = lane & 3;

    for (int tile = blockIdx.x; tile < nT; tile += gridDim.x) {
        const int m0 = tile * 128;
        cpa_wait0();
        __syncthreads();
        convert_A(smem, tid);
        __syncthreads();
        const int next = tile + gridDim.x;
        if (next < nT) prefetch_A_raw(X, sb, next * 128, M, tid);
        cpa_commit();

        float c[2][4][4];
        kloop(sb, aBase, bBase, c);

#pragma unroll
        for (int t = 0; t < 2; t++) {
            const int r0 = m0 + wm * 32 + t * 16 + g;
            const int r1 = r0 + 8;
#pragma unroll
            for (int j = 0; j < 4; j++) {
                const int col = wn * 32 + j * 8 + tg * 2;
                const float2 bb = *(const float2*)(bv + col);
                if (r0 < M)
                    *(float2*)(Y + (size_t)r0 * D + col) =
                        make_float2(c[t][j][0] + bb.x, c[t][j][1] + bb.y);
                if (r1 < M)
                    *(float2*)(Y + (size_t)r1 * D + col) =
                        make_float2(c[t][j][2] + bb.x, c[t][j][3] + bb.y);
            }
        }
    }
}

// -------- persistent HMMA GEMM, segment-sum REDG epilogue --------------------
__global__ void __launch_bounds__(512, 1) gemm_acc_pers_kernel(
    const float* __restrict__ X, const float* __restrict__ bias9, int idx,
    float* __restrict__ acc, const int* __restrict__ grow, int M)
{
    extern __shared__ char smem[];
    const uint32_t sb = smem_u32(smem);
    int* sg = (int*)(smem + OFF_SG);
    const int tid = threadIdx.x, lane = tid & 31, warp = tid >> 5;
    const int wm = warp >> 2, wn = warp & 3;
    const int nT = (M + 127) >> 7;
    if ((int)blockIdx.x >= nT) return;

    prefetch_B(sb, idx, tid);
    prefetch_A_raw(X, sb, blockIdx.x * 128, M, tid);
    prefetch_G(grow, sb, blockIdx.x * 128, M, tid, 0);
    cpa_commit();

    const int lt = lane >> 3, lr = lane & 7;
    uint32_t aBase[2];
#pragma unroll
    for (int t = 0; t < 2; t++)
        aBase[t] = (uint32_t)((wm * 32 + t * 16 + (lt & 1) * 8 + lr) * SA
                              + (lt >> 1) * 8) * 2;
    uint32_t bBase[2];
#pragma unroll
    for (int jj = 0; jj < 2; jj++)
        bBase[jj] = (uint32_t)((wn * 32 + jj * 16 + (lt >> 1) * 8 + lr) * SA
                               + (lt & 1) * 8) * 2;

    const float* bv = bias9 + idx * D;
    const int g = lane >> 2, tg = lane & 3;
    int it = 0;

    for (int tile = blockIdx.x; tile < nT; tile += gridDim.x) {
        const int m0 = tile * 128;
        cpa_wait0();
        __syncthreads();
        convert_A(smem, tid);
        __syncthreads();
        const int next = tile + gridDim.x;
        if (next < nT) {
            prefetch_A_raw(X, sb, next * 128, M, tid);
            prefetch_G(grow, sb, next * 128, M, tid, it ^ 1);
        }
        cpa_commit();

        float c[2][4][4];
        kloop(sb, aBase, bBase, c);

        const int* sgc = sg + it * 128;
#pragma unroll
        for (int t = 0; t < 2; t++) {
#pragma unroll
            for (int ri = 0; ri < 2; ri++) {
                const int lrow = wm * 32 + t * 16 + g + ri * 8;
                const int row  = m0 + lrow;
                const bool valid = row < M;
                float* ap = acc + (size_t)sgc[lrow] * D;
#pragma unroll
                for (int j = 0; j < 4; j++) {
                    const int col = wn * 32 + j * 8 + tg * 2;
                    const float2 bb = *(const float2*)(bv + col);
                    float vx = c[t][j][ri * 2 + 0] + bb.x;
                    float vy = c[t][j][ri * 2 + 1] + bb.y;
                    float ox = __shfl_xor_sync(0xffffffffu, vx, 1);
                    float oy = __shfl_xor_sync(0xffffffffu, vy, 1);
                    if (valid && (tg & 1) == 0)
                        red_add_v4(ap + col, make_float4(vx, vy, ox, oy));
                }
            }
        }
        it ^= 1;
    }
}

// ======================= non-GEMM stages =====================================
__global__ void edge_pre_kernel(const float* __restrict__ Ah,
    float* __restrict__ E1, const float* __restrict__ Cu,
    const int* __restrict__ src, const int* __restrict__ dst,
    const int* __restrict__ a2g, int E)
{
    __shared__ int s_src[EROWS], s_dst[EROWS], s_g[EROWS];
    const int tid = threadIdx.x;
    const int e0  = blockIdx.x * EROWS;
    if (e0 + tid < E) {
        int s = src[e0 + tid];
        s_src[tid] = s;
        s_dst[tid] = dst[e0 + tid];
        s_g[tid]   = a2g[s];
    }
    __syncthreads();
    const int nr = min(EROWS, E - e0);
    float sum = 0.f, sq = 0.f;
    for (int r = 0; r < nr; r++) {
        size_t e = (size_t)(e0 + r);
        float v = E1[e * D + tid]
                + Ah[(size_t)s_src[r] * D + tid]
                + Ah[(size_t)s_dst[r] * D + tid]
                + Cu[(size_t)s_g[r] * D + tid];
        E1[e * D + tid] = v;
        sum += v; sq += v * v;
    }
    atomicAdd(&S_stats[0 * D + tid], sum);
    atomicAdd(&S_stats[1 * D + tid], sq);
}

__global__ void e_norm_gate_kernel(const float* __restrict__ E1,
    const float* __restrict__ gamma, const float* __restrict__ beta,
    float* __restrict__ e_out, const float* __restrict__ Eh,
    const int* __restrict__ src, const int* __restrict__ dst,
    int E, float invE)
{
    __shared__ int s_src[EROWS], s_dst[EROWS];
    const int tid = threadIdx.x;
    const int rl  = tid >> 5;
    const int c4  = (tid & 31) * 4;
    const int e0  = blockIdx.x * EROWS;
    if (e0 + tid < E) { s_src[tid] = src[e0 + tid]; s_dst[tid] = dst[e0 + tid]; }
    __syncthreads();
    float gm[4], bt[4];
#pragma unroll
    for (int i = 0; i < 4; i++) {
        int c = c4 + i;
        float mu  = S_stats[c] * invE;
        float var = S_stats[D + c] * invE - mu * mu;
        float rs  = rsqrtf(var + 1e-5f);
        gm[i] = gamma[D + c] * rs;
        bt[i] = beta[D + c] - mu * gm[i];
    }
    const int nr = min(EROWS, E - e0);
    for (int r = rl; r < nr; r += 4) {
        size_t e = (size_t)(e0 + r);
        float4 x = *(const float4*)(E1 + e * D + c4);
        float4 y;
        y.x = fmaxf(fmaf(x.x, gm[0], bt[0]), 0.f);
        y.y = fmaxf(fmaf(x.y, gm[1], bt[1]), 0.f);
        y.z = fmaxf(fmaf(x.z, gm[2], bt[2]), 0.f);
        y.w = fmaxf(fmaf(x.w, gm[3], bt[3]), 0.f);
        *(float4*)(e_out + e * D + c4) = y;
        float4 sg;
        sg.x = 1.f / (1.f + __expf(-y.x));
        sg.y = 1.f / (1.f + __expf(-y.y));
        sg.z = 1.f / (1.f + __expf(-y.z));
        sg.w = 1.f / (1.f + __expf(-y.w));
        float4 ev = *(const float4*)(Eh + (size_t)s_src[r] * D + c4);
        size_t doff = (size_t)s_dst[r] * D + c4;
        red_add_v4(S_num + doff,
                   make_float4(sg.x * ev.x, sg.y * ev.y, sg.z * ev.z, sg.w * ev.w));
        red_add_v4(S_den + doff, sg);
    }
}

__global__ void h_pre_kernel(float* __restrict__ Dh,
    const float* __restrict__ Fu, const int* __restrict__ a2g, int N)
{
    __shared__ int s_g[EROWS];
    const int tid = threadIdx.x;
    const int n0  = blockIdx.x * EROWS;
    if (n0 + tid < N) s_g[tid] = a2g[n0 + tid];
    __syncthreads();
    const int nr = min(EROWS, N - n0);
    float sum = 0.f, sq = 0.f;
    for (int r = 0; r < nr; r++) {
        size_t n = (size_t)(n0 + r);
        float h1 = S_num[n * D + tid] / (S_den[n * D + tid] + 1e-6f);
        float v  = Dh[n * D + tid] + h1 + Fu[(size_t)s_g[r] * D + tid];
        Dh[n * D + tid] = v;
        sum += v; sq += v * v;
    }
    atomicAdd(&S_stats[2 * D + tid], sum);
    atomicAdd(&S_stats[3 * D + tid], sq);
    if (tid == 0) {
        int gc = -1; float c = 0.f;
        for (int r = 0; r < nr; r++) {
            int g = s_g[r];
            if (g != gc) {
                if (gc >= 0) atomicAdd(&S_cnt[gc], c);
                gc = g; c = 0.f;
            }
            c += 1.f;
        }
        if (gc >= 0) atomicAdd(&S_cnt[gc], c);
    }
}

__global__ void norm_kernel(const float* __restrict__ Xp,
    const float* __restrict__ gamma, const float* __restrict__ beta,
    float* __restrict__ out, int M, float invM, int statRow, int bnRow)
{
    const int tid = threadIdx.x;
    float mu  = S_stats[statRow * D + tid] * invM;
    float var = S_stats[(statRow + 1) * D + tid] * invM - mu * mu;
    float rs  = rsqrtf(var + 1e-5f);
    float gm  = gamma[bnRow * D + tid] * rs;
    float bt  = beta[bnRow * D + tid] - mu * gm;
    const int n0 = blockIdx.x * EROWS;
    const int nr = min(EROWS, M - n0);
    for (int r = 0; r < nr; r++) {
        size_t n = (size_t)(n0 + r);
        out[n * D + tid] = fmaxf(fmaf(Xp[n * D + tid], gm, bt), 0.f);
    }
}

__global__ void u_pre_kernel(float* __restrict__ Iu, int G, float invE)
{
    const int tid = threadIdx.x;
    const int g0  = blockIdx.x * EROWS;
    const int nr  = min(EROWS, G - g0);
    float sum = 0.f, sq = 0.f;
    for (int r = 0; r < nr; r++) {
        size_t g = (size_t)(g0 + r);
        float c  = fmaxf(S_cnt[g], 1.f);
        float v  = S_accG[g * D + tid] / c + S_accHe[g * D + tid] * invE
                 + Iu[g * D + tid];
        Iu[g * D + tid] = v;
        sum += v; sq += v * v;
    }
    atomicAdd(&S_stats[4 * D + tid], sum);
    atomicAdd(&S_stats[5 * D + tid], sq);
}

// ---------------------------- launch -----------------------------------------
extern "C" void kernel_launch(void* const* d_in, const int* in_sizes, int n_in,
                              void* d_out, int out_size)
{
    const float* h     = (const float*)d_in[0];
    const float* e     = (const float*)d_in[1];
    const float* u     = (const float*)d_in[2];
    const float* W     = (const float*)d_in[3];
    const float* b     = (const float*)d_in[4];
    const float* gamma = (const float*)d_in[5];
    const float* beta  = (const float*)d_in[6];
    const int*   src   = (const int*)d_in[7];
    const int*   dst   = (const int*)d_in[8];
    const int*   a2g   = (const int*)d_in[9];

    const int N = in_sizes[0] / D;
    const int E = in_sizes[1] / D;
    const int G = in_sizes[2] / D;

    float* out   = (float*)d_out;
    float* h_out = out;
    float* e_out = out + (size_t)N * D;
    float* u_out = out + (size_t)(N + E) * D;

    cudaFuncSetAttribute(gemm_pers_kernel,
                         cudaFuncAttributeMaxDynamicSharedMemorySize, SMEM_P);
    cudaFuncSetAttribute(gemm_acc_pers_kernel,
                         cudaFuncAttributeMaxDynamicSharedMemorySize, SMEM_PA);

    void *pNum, *pDen, *pAccG, *pAccHe, *pCnt, *pStats;
    cudaGetSymbolAddress(&pNum,   S_num);
    cudaGetSymbolAddress(&pDen,   S_den);
    cudaGetSymbolAddress(&pAccG,  S_accG);
    cudaGetSymbolAddress(&pAccHe, S_accHe);
    cudaGetSymbolAddress(&pCnt,   S_cnt);
    cudaGetSymbolAddress(&pStats, S_stats);
    cudaMemsetAsync(pNum,   0, (size_t)N * D * sizeof(float));
    cudaMemsetAsync(pDen,   0, (size_t)N * D * sizeof(float));
    cudaMemsetAsync(pAccG,  0, (size_t)G * D * sizeof(float));
    cudaMemsetAsync(pAccHe, 0, (size_t)G * D * sizeof(float));
    cudaMemsetAsync(pCnt,   0, (size_t)G * sizeof(float));
    cudaMemsetAsync(pStats, 0, 8 * D * sizeof(float));

    float *dAh, *dDh, *dEh, *dE1, *dCu, *dFu, *dIu;
    int* dDstg;
    cudaGetSymbolAddress((void**)&dAh, S_Ah);
    cudaGetSymbolAddress((void**)&dDh, S_Dh);
    cudaGetSymbolAddress((void**)&dEh, S_Eh);
    cudaGetSymbolAddress((void**)&dE1, S_E1);
    cudaGetSymbolAddress((void**)&dCu, S_Cu);
    cudaGetSymbolAddress((void**)&dFu, S_Fu);
    cudaGetSymbolAddress((void**)&dIu, S_Iu);
    cudaGetSymbolAddress((void**)&dDstg, S_dstg);

    const int gN  = (N + 127) / 128;
    const int gE  = (E + 127) / 128;
    const int gG  = (G + 127) / 128;
    const int pN  = gN < 148 ? gN : 148;
    const int pE  = gE < 148 ? gE : 148;
    const int pG  = gG < 148 ? gG : 148;

    prep_w_kernel<<<(9 * D * D + 255) / 256, 256>>>(W);
    dstg_kernel<<<(E + 255) / 256, 256>>>(dst, a2g, E);

    // upfront GEMMs (persistent, pipelined)
    gemm_pers_kernel<<<pN, 512, SMEM_P>>>(h, b, 0, dAh, N);  // A(h)
    gemm_pers_kernel<<<pN, 512, SMEM_P>>>(h, b, 3, dDh, N);  // D(h)
    gemm_pers_kernel<<<pN, 512, SMEM_P>>>(h, b, 4, dEh, N);  // E(h)
    gemm_pers_kernel<<<pG, 512, SMEM_P>>>(u, b, 2, dCu, G);  // C(u)
    gemm_pers_kernel<<<pG, 512, SMEM_P>>>(u, b, 5, dFu, G);  // F(u)
    gemm_pers_kernel<<<pG, 512, SMEM_P>>>(u, b, 8, dIu, G);  // I(u)
    gemm_pers_kernel<<<pE, 512, SMEM_P>>>(e, b, 1, dE1, E);  // B(e)

    // edge update
    edge_pre_kernel<<<gE, EROWS>>>(dAh, dE1, dCu, src, dst, a2g, E);
    e_norm_gate_kernel<<<gE, EROWS>>>(dE1, gamma, beta, e_out, dEh, src, dst,
                                      E, 1.f / (float)E);

    // atom update (h_pre also accumulates per-graph atom counts)
    h_pre_kernel<<<gN, EROWS>>>(dDh, dFu, a2g, N);
    norm_kernel<<<gN, EROWS>>>(dDh, gamma, beta, h_out, N, 1.f / (float)N, 2, 0);

    // global update: GEMMs with fused segment-sum scatter
    gemm_acc_pers_kernel<<<pN, 512, SMEM_PA>>>(h_out, b, 6, (float*)pAccG,
                                               a2g, N);      // G(h_new)
    gemm_acc_pers_kernel<<<pE, 512, SMEM_PA>>>(e_out, b, 7, (float*)pAccHe,
                                               dDstg, E);    // H(e_new)
    u_pre_kernel<<<gG, EROWS>>>(dIu, G, 1.f / (float)E);
    norm_kernel<<<gG, EROWS>>>(dIu, gamma, beta, u_out, G, 1.f / (float)G, 4, 2);
}

// round 17
// speedup vs baseline: 1.2180x; 1.2180x over previous
#include <cuda_runtime.h>
#include <cuda_bf16.h>
#include <math.h>
#include <stdint.h>

#define D      128
#define NMAX   200000
#define EMAX   600000
#define GMAX   10000
#define EROWS  128
#define SA     136          // smem tile stride in bf16 elements

// ---------------- scratch (device globals; no runtime allocation) -----------
__device__ float S_Ah [(size_t)NMAX * D];
__device__ float S_Dh [(size_t)NMAX * D];
__device__ float S_Eh [(size_t)NMAX * D];
__device__ float S_num[(size_t)NMAX * D];
__device__ float S_den[(size_t)NMAX * D];
__device__ float S_E1 [(size_t)EMAX * D];
__device__ float S_Cu [(size_t)GMAX * D];
__device__ float S_Fu [(size_t)GMAX * D];
__device__ float S_Iu [(size_t)GMAX * D];
__device__ float S_accG [(size_t)GMAX * D];
__device__ float S_accHe[(size_t)GMAX * D];
__device__ float S_cnt[GMAX];
__device__ float S_stats[8 * D];
__device__ int   S_dstg[EMAX];
// bf16 split weights [9][n][k] and split activations (h | e | u slots)
__device__ __align__(16) __nv_bfloat16 S_Wh[9 * D * D];
__device__ __align__(16) __nv_bfloat16 S_Wl[9 * D * D];
__device__ __align__(16) __nv_bfloat16 S_XH[(size_t)(NMAX + EMAX + GMAX) * D];
__device__ __align__(16) __nv_bfloat16 S_XL[(size_t)(NMAX + EMAX + GMAX) * D];

// ---------------- helpers ----------------------------------------------------
__device__ __forceinline__ uint32_t smem_u32(const void* p) {
    uint32_t a;
    asm("{ .reg .u64 t; cvta.to.shared.u64 t, %1; cvt.u32.u64 %0, t; }"
        : "=r"(a) : "l"(p));
    return a;
}
__device__ __forceinline__ void ldm_x4(uint32_t& r0, uint32_t& r1,
                                       uint32_t& r2, uint32_t& r3, uint32_t a) {
    asm volatile("ldmatrix.sync.aligned.m8n8.x4.shared.b16 {%0,%1,%2,%3}, [%4];"
                 : "=r"(r0), "=r"(r1), "=r"(r2), "=r"(r3) : "r"(a));
}
__device__ __forceinline__ void mma16816(float* c, const uint32_t* a,
                                         const uint32_t* b) {
    asm volatile(
        "mma.sync.aligned.m16n8k16.row.col.f32.bf16.bf16.f32 "
        "{%0,%1,%2,%3}, {%4,%5,%6,%7}, {%8,%9}, {%0,%1,%2,%3};"
        : "+f"(c[0]), "+f"(c[1]), "+f"(c[2]), "+f"(c[3])
        : "r"(a[0]), "r"(a[1]), "r"(a[2]), "r"(a[3]), "r"(b[0]), "r"(b[1]));
}
__device__ __forceinline__ void red_add_v4(float* p, float4 v) {
    asm volatile("red.global.add.v4.f32 [%0], {%1,%2,%3,%4};"
                 :: "l"(p), "f"(v.x), "f"(v.y), "f"(v.z), "f"(v.w) : "memory");
}
__device__ __forceinline__ void cpa16(uint32_t dst, const void* src) {
    asm volatile("cp.async.cg.shared.global [%0], [%1], 16;"
                 :: "r"(dst), "l"(src) : "memory");
}
__device__ __forceinline__ void cpa16z(uint32_t dst, const void* src, int sb) {
    asm volatile("cp.async.cg.shared.global [%0], [%1], 16, %2;"
                 :: "r"(dst), "l"(src), "r"(sb) : "memory");
}
__device__ __forceinline__ void cpa_commit() {
    asm volatile("cp.async.commit_group;" ::: "memory");
}
__device__ __forceinline__ void cpa_wait0() {
    asm volatile("cp.async.wait_group 0;" ::: "memory");
}
__device__ __forceinline__ void cpa_wait1() {
    asm volatile("cp.async.wait_group 1;" ::: "memory");
}

#define TILE   34816                       // 128 * SA * 2
// gemm3 (multi-weight): AH|AL|BUF0(BH,BL)|BUF1
#define G3_A   0
#define G3_B0  (2 * TILE)
#define G3_B1  (4 * TILE)
#define SMEM_G3 (6 * TILE)                 // 208896
// gemm1p (persistent): A0|A1|B
#define P_A0   0
#define P_A1   (2 * TILE)
#define P_B    (4 * TILE)
#define SMEM_P  (6 * TILE)                 // 208896
#define P_SG   (6 * TILE)
#define SMEM_PA (6 * TILE + 1024)          // 209920

// -------- prep kernels -------------------------------------------------------
__global__ void prep_w_kernel(const float* __restrict__ W) {
    int t = blockIdx.x * 256 + threadIdx.x;
    if (t >= 9 * D * D) return;
    int i = t >> 14, rem = t & 16383, n = rem >> 7, k = rem & 127;
    float v = W[(i << 14) + (k << 7) + n];
    __nv_bfloat16 h = __float2bfloat16(v);
    S_Wh[t] = h;
    S_Wl[t] = __float2bfloat16(v - __bfloat162float(h));
}
__global__ void prep_split_kernel(const float* __restrict__ X, size_t off,
                                  int total) {
    int i = blockIdx.x * 256 + threadIdx.x;
    if (i >= total) return;
    float v = X[i];
    __nv_bfloat16 h = __float2bfloat16(v);
    S_XH[off + i] = h;
    S_XL[off + i] = __float2bfloat16(v - __bfloat162float(h));
}
__global__ void dstg_kernel(const int* __restrict__ dst,
                            const int* __restrict__ a2g, int E) {
    int i = blockIdx.x * 256 + threadIdx.x;
    if (i < E) S_dstg[i] = a2g[dst[i]];
}

// ---- building blocks --------------------------------------------------------
__device__ __forceinline__ void cpa_tile(const __nv_bfloat16* __restrict__ src,
                                         uint32_t dsm, int m0, int M, int tid) {
    // copy one 128x128 bf16 tile (rows m0..) into smem stride SA
    const int row = tid >> 2, q = tid & 3;
    const int gr = m0 + row;
    const int ok = (gr < M) ? 16 : 0;
    const __nv_bfloat16* sr = src + (size_t)(ok ? gr : 0) * D + q * 32;
    uint32_t dr = dsm + (uint32_t)(row * SA + q * 32) * 2;
#pragma unroll
    for (int j = 0; j < 4; j++) cpa16z(dr + j * 16, sr + j * 8, ok);
}
__device__ __forceinline__ void cpa_B(uint32_t sb, uint32_t off, int idx,
                                      int tid) {
    const int n = tid >> 2, q = tid & 3;
    const __nv_bfloat16* sH = S_Wh + (size_t)idx * 16384 + n * 128 + q * 32;
    const __nv_bfloat16* sL = S_Wl + (size_t)idx * 16384 + n * 128 + q * 32;
    uint32_t dH = sb + off + (uint32_t)(n * SA + q * 32) * 2;
    uint32_t dL = dH + TILE;
#pragma unroll
    for (int j = 0; j < 4; j++) {
        cpa16(dH + j * 16, sH + j * 8);
        cpa16(dL + j * 16, sL + j * 8);
    }
}

__device__ __forceinline__ void kloop(uint32_t aSm, uint32_t bSm,
                                      const uint32_t* aBase,
                                      const uint32_t* bBase, float c[2][4][4]) {
#pragma unroll
    for (int t = 0; t < 2; t++)
#pragma unroll
        for (int j = 0; j < 4; j++)
#pragma unroll
            for (int q = 0; q < 4; q++) c[t][j][q] = 0.f;
#pragma unroll
    for (int ks = 0; ks < 8; ks++) {
        const uint32_t ko = (uint32_t)(ks * 16) * 2;
        uint32_t ah[2][4], al[2][4];
#pragma unroll
        for (int t = 0; t < 2; t++) {
            ldm_x4(ah[t][0], ah[t][1], ah[t][2], ah[t][3], aSm + aBase[t] + ko);
            ldm_x4(al[t][0], al[t][1], al[t][2], al[t][3],
                   aSm + TILE + aBase[t] + ko);
        }
        uint32_t bh[4][2], bl[4][2];
#pragma unroll
        for (int jj = 0; jj < 2; jj++) {
            uint32_t r0, r1, r2, r3;
            ldm_x4(r0, r1, r2, r3, bSm + bBase[jj] + ko);
            bh[jj * 2 + 0][0] = r0; bh[jj * 2 + 0][1] = r1;
            bh[jj * 2 + 1][0] = r2; bh[jj * 2 + 1][1] = r3;
            ldm_x4(r0, r1, r2, r3, bSm + TILE + bBase[jj] + ko);
            bl[jj * 2 + 0][0] = r0; bl[jj * 2 + 0][1] = r1;
            bl[jj * 2 + 1][0] = r2; bl[jj * 2 + 1][1] = r3;
        }
#pragma unroll
        for (int t = 0; t < 2; t++)
#pragma unroll
            for (int j = 0; j < 4; j++) {
                mma16816(c[t][j], ah[t], bh[j]);
                mma16816(c[t][j], ah[t], bl[j]);
                mma16816(c[t][j], al[t], bh[j]);
            }
    }
}
__device__ __forceinline__ void calc_bases(int lane, int wm, int wn,
                                           uint32_t* aBase, uint32_t* bBase) {
    const int lt = lane >> 3, lr = lane & 7;
#pragma unroll
    for (int t = 0; t < 2; t++)
        aBase[t] = (uint32_t)((wm * 32 + t * 16 + (lt & 1) * 8 + lr) * SA
                              + (lt >> 1) * 8) * 2;
#pragma unroll
    for (int jj = 0; jj < 2; jj++)
        bBase[jj] = (uint32_t)((wn * 32 + jj * 16 + (lt >> 1) * 8 + lr) * SA
                               + (lt & 1) * 8) * 2;
}

// -------- multi-weight GEMM (R11 shape, async A) -----------------------------
__global__ void __launch_bounds__(512, 1) gemm3_kernel(
    const __nv_bfloat16* __restrict__ XH, const __nv_bfloat16* __restrict__ XL,
    const float* __restrict__ bias9, int i0, int i1, int i2,
    float* __restrict__ Y0, float* __restrict__ Y1, float* __restrict__ Y2,
    int M)
{
    extern __shared__ char smem[];
    const uint32_t sb = smem_u32(smem);
    const int tid = threadIdx.x, lane = tid & 31, warp = tid >> 5;
    const int wm = warp >> 2, wn = warp & 3;
    const int m0 = blockIdx.x * 128;
    const int idxs[3] = {i0, i1, i2};
    float* const outs[3] = {Y0, Y1, Y2};
    const int nW = (i1 < 0) ? 1 : ((i2 < 0) ? 2 : 3);

    cpa_tile(XH, sb + G3_A, m0, M, tid);
    cpa_tile(XL, sb + G3_A + TILE, m0, M, tid);
    cpa_B(sb, G3_B0, idxs[0], tid);
    cpa_commit();

    uint32_t aBase[2], bBase[2];
    calc_bases(lane, wm, wn, aBase, bBase);
    const int g = lane >> 2, tg = lane & 3;

    for (int w = 0; w < nW; w++) {
        if (w + 1 < nW) {
            cpa_B(sb, (w & 1) ? G3_B0 : G3_B1, idxs[w + 1], tid);
            cpa_commit();
            cpa_wait1();
        } else {
            cpa_wait0();
        }
        __syncthreads();

        float c[2][4][4];
        kloop(sb + G3_A, sb + ((w & 1) ? G3_B1 : G3_B0), aBase, bBase, c);

        float* Y = outs[w];
        const float* bv = bias9 + idxs[w] * D;
#pragma unroll
        for (int t = 0; t < 2; t++) {
            const int r0 = m0 + wm * 32 + t * 16 + g;
            const int r1 = r0 + 8;
#pragma unroll
            for (int j = 0; j < 4; j++) {
                const int col = wn * 32 + j * 8 + tg * 2;
                const float2 bb = *(const float2*)(bv + col);
                if (r0 < M)
                    *(float2*)(Y + (size_t)r0 * D + col) =
                        make_float2(c[t][j][0] + bb.x, c[t][j][1] + bb.y);
                if (r1 < M)
                    *(float2*)(Y + (size_t)r1 * D + col) =
                        make_float2(c[t][j][2] + bb.x, c[t][j][3] + bb.y);
            }
        }
        __syncthreads();
    }
}

// -------- persistent single-weight GEMM, dense output ------------------------
__global__ void __launch_bounds__(512, 1) gemm_p_kernel(
    const __nv_bfloat16* __restrict__ XH, const __nv_bfloat16* __restrict__ XL,
    const float* __restrict__ bias9, int idx, float* __restrict__ Y, int M)
{
    extern __shared__ char smem[];
    const uint32_t sb = smem_u32(smem);
    const int tid = threadIdx.x, lane = tid & 31, warp = tid >> 5;
    const int wm = warp >> 2, wn = warp & 3;
    const int nT = (M + 127) >> 7;
    const int gsz = gridDim.x;
    if ((int)blockIdx.x >= nT) return;

    cpa_B(sb, P_B, idx, tid);
    cpa_tile(XH, sb + P_A0, blockIdx.x * 128, M, tid);
    cpa_tile(XL, sb + P_A0 + TILE, blockIdx.x * 128, M, tid);
    cpa_commit();
    if ((int)blockIdx.x + gsz < nT) {
        cpa_tile(XH, sb + P_A1, (blockIdx.x + gsz) * 128, M, tid);
        cpa_tile(XL, sb + P_A1 + TILE, (blockIdx.x + gsz) * 128, M, tid);
        cpa_commit();
    }

    uint32_t aBase[2], bBase[2];
    calc_bases(lane, wm, wn, aBase, bBase);
    const float* bv = bias9 + idx * D;
    const int g = lane >> 2, tg = lane & 3;
    int buf = 0;

    for (int tile = blockIdx.x; tile < nT; tile += gsz) {
        const int m0 = tile * 128;
        if (tile + gsz < nT) cpa_wait1(); else cpa_wait0();
        __syncthreads();

        float c[2][4][4];
        kloop(sb + (buf ? P_A1 : P_A0), sb + P_B, aBase, bBase, c);
        __syncthreads();
        if (tile + 2 * gsz < nT) {
            uint32_t ao = buf ? P_A1 : P_A0;
            cpa_tile(XH, sb + ao, (tile + 2 * gsz) * 128, M, tid);
            cpa_tile(XL, sb + ao + TILE, (tile + 2 * gsz) * 128, M, tid);
            cpa_commit();
        }

#pragma unroll
        for (int t = 0; t < 2; t++) {
            const int r0 = m0 + wm * 32 + t * 16 + g;
            const int r1 = r0 + 8;
#pragma unroll
            for (int j = 0; j < 4; j++) {
                const int col = wn * 32 + j * 8 + tg * 2;
                const float2 bb = *(const float2*)(bv + col);
                if (r0 < M)
                    *(float2*)(Y + (size_t)r0 * D + col) =
                        make_float2(c[t][j][0] + bb.x, c[t][j][1] + bb.y);
                if (r1 < M)
                    *(float2*)(Y + (size_t)r1 * D + col) =
                        make_float2(c[t][j][2] + bb.x, c[t][j][3] + bb.y);
            }
        }
        buf ^= 1;
    }
}

// -------- persistent single-weight GEMM, REDG segment-sum epilogue -----------
__global__ void __launch_bounds__(512, 1) gemm_pacc_kernel(
    const __nv_bfloat16* __restrict__ XH, const __nv_bfloat16* __restrict__ XL,
    const float* __restrict__ bias9, int idx, float* __restrict__ acc,
    const int* __restrict__ grow, int M)
{
    extern __shared__ char smem[];
    const uint32_t sb = smem_u32(smem);
    int* sg = (int*)(smem + P_SG);
    const int tid = threadIdx.x, lane = tid & 31, warp = tid >> 5;
    const int wm = warp >> 2, wn = warp & 3;
    const int nT = (M + 127) >> 7;
    const int gsz = gridDim.x;
    if ((int)blockIdx.x >= nT) return;

    auto pre_g = [&](int m0, int buf) {
        if (tid < 32) {
            int r0 = m0 + tid * 4;
            int rem = M - r0;
            int bytes = (rem >= 4) ? 16 : ((rem > 0) ? rem * 4 : 0);
            cpa16z(sb + P_SG + buf * 512 + tid * 16,
                   grow + (bytes > 0 ? r0 : 0), bytes);
        }
    };

    cpa_B(sb, P_B, idx, tid);
    cpa_tile(XH, sb + P_A0, blockIdx.x * 128, M, tid);
    cpa_tile(XL, sb + P_A0 + TILE, blockIdx.x * 128, M, tid);
    pre_g(blockIdx.x * 128, 0);
    cpa_commit();
    if ((int)blockIdx.x + gsz < nT) {
        cpa_tile(XH, sb + P_A1, (blockIdx.x + gsz) * 128, M, tid);
        cpa_tile(XL, sb + P_A1 + TILE, (blockIdx.x + gsz) * 128, M, tid);
        pre_g((blockIdx.x + gsz) * 128, 1);
        cpa_commit();
    }

    uint32_t aBase[2], bBase[2];
    calc_bases(lane, wm, wn, aBase, bBase);
    const float* bv = bias9 + idx * D;
    const int g = lane >> 2, tg = lane & 3;
    int buf = 0;

    for (int tile = blockIdx.x; tile < nT; tile += gsz) {
        const int m0 = tile * 128;
        if (tile + gsz < nT) cpa_wait1(); else cpa_wait0();
        __syncthreads();

        // latch this tile's graph indices before the buffer is re-prefetched
        int gidx[2][2];
#pragma unroll
        for (int t = 0; t < 2; t++)
#pragma unroll
            for (int ri = 0; ri < 2; ri++)
                gidx[t][ri] = sg[buf * 128 + wm * 32 + t * 16 + g + ri * 8];

        float c[2][4][4];
        kloop(sb + (buf ? P_A1 : P_A0), sb + P_B, aBase, bBase, c);
        __syncthreads();
        if (tile + 2 * gsz < nT) {
            uint32_t ao = buf ? P_A1 : P_A0;
            cpa_tile(XH, sb + ao, (tile + 2 * gsz) * 128, M, tid);
            cpa_tile(XL, sb + ao + TILE, (tile + 2 * gsz) * 128, M, tid);
            pre_g((tile + 2 * gsz) * 128, buf);
            cpa_commit();
        }

#pragma unroll
        for (int t = 0; t < 2; t++) {
#pragma unroll
            for (int ri = 0; ri < 2; ri++) {
                const int row = m0 + wm * 32 + t * 16 + g + ri * 8;
                const bool valid = row < M;
                float* ap = acc + (size_t)gidx[t][ri] * D;
#pragma unroll
                for (int j = 0; j < 4; j++) {
                    const int col = wn * 32 + j * 8 + tg * 2;
                    const float2 bb = *(const float2*)(bv + col);
                    float vx = c[t][j][ri * 2 + 0] + bb.x;
                    float vy = c[t][j][ri * 2 + 1] + bb.y;
                    float ox = __shfl_xor_sync(0xffffffffu, vx, 1);
                    float oy = __shfl_xor_sync(0xffffffffu, vy, 1);
                    if (valid && (tg & 1) == 0)
                        red_add_v4(ap + col, make_float4(vx, vy, ox, oy));
                }
            }
        }
        buf ^= 1;
    }
}

// ======================= non-GEMM stages =====================================
__global__ void edge_pre_kernel(const float* __restrict__ Ah,
    float* __restrict__ E1, const float* __restrict__ Cu,
    const int* __restrict__ src, const int* __restrict__ dst,
    const int* __restrict__ a2g, int E)
{
    __shared__ int s_src[EROWS], s_dst[EROWS], s_g[EROWS];
    const int tid = threadIdx.x;
    const int e0  = blockIdx.x * EROWS;
    if (e0 + tid < E) {
        int s = src[e0 + tid];
        s_src[tid] = s;
        s_dst[tid] = dst[e0 + tid];
        s_g[tid]   = a2g[s];
    }
    __syncthreads();
    const int nr = min(EROWS, E - e0);
    float sum = 0.f, sq = 0.f;
    for (int r = 0; r < nr; r++) {
        size_t e = (size_t)(e0 + r);
        float v = E1[e * D + tid]
                + Ah[(size_t)s_src[r] * D + tid]
                + Ah[(size_t)s_dst[r] * D + tid]
                + Cu[(size_t)s_g[r] * D + tid];
        E1[e * D + tid] = v;
        sum += v; sq += v * v;
    }
    atomicAdd(&S_stats[0 * D + tid], sum);
    atomicAdd(&S_stats[1 * D + tid], sq);
}

// norm+sigmoid+scatter; also emits bf16 hi/lo of e_out for the H GEMM
__global__ void e_norm_gate_kernel(const float* __restrict__ E1,
    const float* __restrict__ gamma, const float* __restrict__ beta,
    float* __restrict__ e_out, __nv_bfloat16* __restrict__ eH,
    __nv_bfloat16* __restrict__ eL, const float* __restrict__ Eh,
    const int* __restrict__ src, const int* __restrict__ dst,
    int E, float invE)
{
    __shared__ int s_src[EROWS], s_dst[EROWS];
    const int tid = threadIdx.x;
    const int rl  = tid >> 5;
    const int c4  = (tid & 31) * 4;
    const int e0  = blockIdx.x * EROWS;
    if (e0 + tid < E) { s_src[tid] = src[e0 + tid]; s_dst[tid] = dst[e0 + tid]; }
    __syncthreads();
    float gm[4], bt[4];
#pragma unroll
    for (int i = 0; i < 4; i++) {
        int c = c4 + i;
        float mu  = S_stats[c] * invE;
        float var = S_stats[D + c] * invE - mu * mu;
        float rs  = rsqrtf(var + 1e-5f);
        gm[i] = gamma[D + c] * rs;
        bt[i] = beta[D + c] - mu * gm[i];
    }
    const int nr = min(EROWS, E - e0);
    for (int r = rl; r < nr; r += 4) {
        size_t e = (size_t)(e0 + r);
        float4 x = *(const float4*)(E1 + e * D + c4);
        float4 y;
        y.x = fmaxf(fmaf(x.x, gm[0], bt[0]), 0.f);
        y.y = fmaxf(fmaf(x.y, gm[1], bt[1]), 0.f);
        y.z = fmaxf(fmaf(x.z, gm[2], bt[2]), 0.f);
        y.w = fmaxf(fmaf(x.w, gm[3], bt[3]), 0.f);
        *(float4*)(e_out + e * D + c4) = y;
        __nv_bfloat16 h0 = __float2bfloat16(y.x), h1 = __float2bfloat16(y.y);
        __nv_bfloat16 h2 = __float2bfloat16(y.z), h3 = __float2bfloat16(y.w);
        *(__nv_bfloat162*)(eH + e * D + c4)     = __nv_bfloat162(h0, h1);
        *(__nv_bfloat162*)(eH + e * D + c4 + 2) = __nv_bfloat162(h2, h3);
        *(__nv_bfloat162*)(eL + e * D + c4) = __nv_bfloat162(
            __float2bfloat16(y.x - __bfloat162float(h0)),
            __float2bfloat16(y.y - __bfloat162float(h1)));
        *(__nv_bfloat162*)(eL + e * D + c4 + 2) = __nv_bfloat162(
            __float2bfloat16(y.z - __bfloat162float(h2)),
            __float2bfloat16(y.w - __bfloat162float(h3)));
        float4 sg;
        sg.x = 1.f / (1.f + __expf(-y.x));
        sg.y = 1.f / (1.f + __expf(-y.y));
        sg.z = 1.f / (1.f + __expf(-y.z));
        sg.w = 1.f / (1.f + __expf(-y.w));
        float4 ev = *(const float4*)(Eh + (size_t)s_src[r] * D + c4);
        size_t doff = (size_t)s_dst[r] * D + c4;
        red_add_v4(S_num + doff,
                   make_float4(sg.x * ev.x, sg.y * ev.y, sg.z * ev.z, sg.w * ev.w));
        red_add_v4(S_den + doff, sg);
    }
}

__global__ void h_pre_kernel(float* __restrict__ Dh,
    const float* __restrict__ Fu, const int* __restrict__ a2g, int N)
{
    __shared__ int s_g[EROWS];
    const int tid = threadIdx.x;
    const int n0  = blockIdx.x * EROWS;
    if (n0 + tid < N) s_g[tid] = a2g[n0 + tid];
    __syncthreads();
    const int nr = min(EROWS, N - n0);
    float sum = 0.f, sq = 0.f;
    for (int r = 0; r < nr; r++) {
        size_t n = (size_t)(n0 + r);
        float h1 = S_num[n * D + tid] / (S_den[n * D + tid] + 1e-6f);
        float v  = Dh[n * D + tid] + h1 + Fu[(size_t)s_g[r] * D + tid];
        Dh[n * D + tid] = v;
        sum += v; sq += v * v;
    }
    atomicAdd(&S_stats[2 * D + tid], sum);
    atomicAdd(&S_stats[3 * D + tid], sq);
    if (tid == 0) {
        int gc = -1; float c = 0.f;
        for (int r = 0; r < nr; r++) {
            int g = s_g[r];
            if (g != gc) {
                if (gc >= 0) atomicAdd(&S_cnt[gc], c);
                gc = g; c = 0.f;
            }
            c += 1.f;
        }
        if (gc >= 0) atomicAdd(&S_cnt[gc], c);
    }
}

// BN+ReLU; optionally emits bf16 hi/lo of result
__global__ void norm_kernel(const float* __restrict__ Xp,
    const float* __restrict__ gamma, const float* __restrict__ beta,
    float* __restrict__ out, __nv_bfloat16* __restrict__ oH,
    __nv_bfloat16* __restrict__ oL, int M, float invM, int statRow, int bnRow)
{
    const int tid = threadIdx.x;
    float mu  = S_stats[statRow * D + tid] * invM;
    float var = S_stats[(statRow + 1) * D + tid] * invM - mu * mu;
    float rs  = rsqrtf(var + 1e-5f);
    float gm  = gamma[bnRow * D + tid] * rs;
    float bt  = beta[bnRow * D + tid] - mu * gm;
    const int n0 = blockIdx.x * EROWS;
    const int nr = min(EROWS, M - n0);
    for (int r = 0; r < nr; r++) {
        size_t n = (size_t)(n0 + r);
        float v = fmaxf(fmaf(Xp[n * D + tid], gm, bt), 0.f);
        out[n * D + tid] = v;
        if (oH) {
            __nv_bfloat16 h = __float2bfloat16(v);
            oH[n * D + tid] = h;
            oL[n * D + tid] = __float2bfloat16(v - __bfloat162float(h));
        }
    }
}

__global__ void u_pre_kernel(float* __restrict__ Iu, int G, float invE)
{
    const int tid = threadIdx.x;
    const int g0  = blockIdx.x * EROWS;
    const int nr  = min(EROWS, G - g0);
    float sum = 0.f, sq = 0.f;
    for (int r = 0; r < nr; r++) {
        size_t g = (size_t)(g0 + r);
        float c  = fmaxf(S_cnt[g], 1.f);
        float v  = S_accG[g * D + tid] / c + S_accHe[g * D + tid] * invE
                 + Iu[g * D + tid];
        Iu[g * D + tid] = v;
        sum += v; sq += v * v;
    }
    atomicAdd(&S_stats[4 * D + tid], sum);
    atomicAdd(&S_stats[5 * D + tid], sq);
}

// ---------------------------- launch -----------------------------------------
extern "C" void kernel_launch(void* const* d_in, const int* in_sizes, int n_in,
                              void* d_out, int out_size)
{
    const float* h     = (const float*)d_in[0];
    const float* e     = (const float*)d_in[1];
    const float* u     = (const float*)d_in[2];
    const float* W     = (const float*)d_in[3];
    const float* b     = (const float*)d_in[4];
    const float* gamma = (const float*)d_in[5];
    const float* beta  = (const float*)d_in[6];
    const int*   src   = (const int*)d_in[7];
    const int*   dst   = (const int*)d_in[8];
    const int*   a2g   = (const int*)d_in[9];

    const int N = in_sizes[0] / D;
    const int E = in_sizes[1] / D;
    const int G = in_sizes[2] / D;

    float* out   = (float*)d_out;
    float* h_out = out;
    float* e_out = out + (size_t)N * D;
    float* u_out = out + (size_t)(N + E) * D;

    cudaFuncSetAttribute(gemm3_kernel,
                         cudaFuncAttributeMaxDynamicSharedMemorySize, SMEM_G3);
    cudaFuncSetAttribute(gemm_p_kernel,
                         cudaFuncAttributeMaxDynamicSharedMemorySize, SMEM_P);
    cudaFuncSetAttribute(gemm_pacc_kernel,
                         cudaFuncAttributeMaxDynamicSharedMemorySize, SMEM_PA);

    void *pNum, *pDen, *pAccG, *pAccHe, *pCnt, *pStats;
    cudaGetSymbolAddress(&pNum,   S_num);
    cudaGetSymbolAddress(&pDen,   S_den);
    cudaGetSymbolAddress(&pAccG,  S_accG);
    cudaGetSymbolAddress(&pAccHe, S_accHe);
    cudaGetSymbolAddress(&pCnt,   S_cnt);
    cudaGetSymbolAddress(&pStats, S_stats);
    cudaMemsetAsync(pNum,   0, (size_t)N * D * sizeof(float));
    cudaMemsetAsync(pDen,   0, (size_t)N * D * sizeof(float));
    cudaMemsetAsync(pAccG,  0, (size_t)G * D * sizeof(float));
    cudaMemsetAsync(pAccHe, 0, (size_t)G * D * sizeof(float));
    cudaMemsetAsync(pCnt,   0, (size_t)G * sizeof(float));
    cudaMemsetAsync(pStats, 0, 8 * D * sizeof(float));

    float *dAh, *dDh, *dEh, *dE1, *dCu, *dFu, *dIu;
    int* dDstg;
    __nv_bfloat16 *dXH, *dXL;
    cudaGetSymbolAddress((void**)&dAh, S_Ah);
    cudaGetSymbolAddress((void**)&dDh, S_Dh);
    cudaGetSymbolAddress((void**)&dEh, S_Eh);
    cudaGetSymbolAddress((void**)&dE1, S_E1);
    cudaGetSymbolAddress((void**)&dCu, S_Cu);
    cudaGetSymbolAddress((void**)&dFu, S_Fu);
    cudaGetSymbolAddress((void**)&dIu, S_Iu);
    cudaGetSymbolAddress((void**)&dDstg, S_dstg);
    cudaGetSymbolAddress((void**)&dXH, S_XH);
    cudaGetSymbolAddress((void**)&dXL, S_XL);

    const size_t offE = (size_t)NMAX * D;
    const size_t offU = (size_t)(NMAX + EMAX) * D;
    const int gN = (N + 127) / 128;
    const int gE = (E + 127) / 128;
    const int gG = (G + 127) / 128;
    const int pE = gE < 148 ? gE : 148;
    const int pN = gN < 148 ? gN : 148;

    // prep: weight split, activation splits, dst-graph map
    prep_w_kernel<<<(9 * D * D + 255) / 256, 256>>>(W);
    prep_split_kernel<<<(N * D + 255) / 256, 256>>>(h, 0, N * D);
    prep_split_kernel<<<(E * D + 255) / 256, 256>>>(e, offE, E * D);
    prep_split_kernel<<<(G * D + 255) / 256, 256>>>(u, offU, G * D);
    dstg_kernel<<<(E + 255) / 256, 256>>>(dst, a2g, E);

    // upfront GEMMs
    gemm3_kernel<<<gN, 512, SMEM_G3>>>(dXH, dXL, b, 0, 3, 4,
                                       dAh, dDh, dEh, N);           // A,D,E
    gemm3_kernel<<<gG, 512, SMEM_G3>>>(dXH + offU, dXL + offU, b, 2, 5, 8,
                                       dCu, dFu, dIu, G);           // C,F,I
    gemm_p_kernel<<<pE, 512, SMEM_P>>>(dXH + offE, dXL + offE, b, 1,
                                       dE1, E);                     // B(e)

    // edge update
    edge_pre_kernel<<<gE, EROWS>>>(dAh, dE1, dCu, src, dst, a2g, E);
    e_norm_gate_kernel<<<gE, EROWS>>>(dE1, gamma, beta, e_out,
                                      dXH + offE, dXL + offE, dEh,
                                      src, dst, E, 1.f / (float)E);

    // atom update
    h_pre_kernel<<<gN, EROWS>>>(dDh, dFu, a2g, N);
    norm_kernel<<<gN, EROWS>>>(dDh, gamma, beta, h_out, dXH, dXL,
                               N, 1.f / (float)N, 2, 0);

    // global update: persistent GEMMs with fused segment-sum scatter
    gemm_pacc_kernel<<<pN, 512, SMEM_PA>>>(dXH, dXL, b, 6, (float*)pAccG,
                                           a2g, N);                 // G(h_new)
    gemm_pacc_kernel<<<pE, 512, SMEM_PA>>>(dXH + offE, dXL + offE, b, 7,
                                           (float*)pAccHe, dDstg, E); // H(e_new)
    u_pre_kernel<<<gG, EROWS>>>(dIu, G, 1.f / (float)E);
    norm_kernel<<<gG, EROWS>>>(dIu, gamma, beta, u_out,
                               (__nv_bfloat16*)0, (__nv_bfloat16*)0,
                               G, 1.f / (float)G, 4, 2);
}